// round 8
// baseline (speedup 1.0000x reference)
#include <cuda_runtime.h>
#include <math.h>

#define B  32
#define L  2048
#define H  1024
#define K2 2048   // 2*H

#define GS 16     // g-splits for u
#define HS 16     // h-splits for v

// Scratch (no allocations allowed anywhere)
__device__ float g_part_u[GS * B * H];    // 2 MB  (L2-hot)
__device__ float g_u[B * H];              // 128 KB
__device__ float g_part_v[HS * B * K2];   // 4 MB  (L2-hot)
__device__ float g_v[B * K2];             // 256 KB
__device__ float g_scores[B * L];         // 256 KB

// Arrival counters (zero-init; every kernel leaves them at zero -> replay-safe)
__device__ unsigned cnt_u1[8],  cnt_u2[8];
__device__ unsigned cnt_v1[16], cnt_v2[16];
__device__ unsigned cnt_s[B];

// ---------------------------------------------------------------------------
// Kernel 1: u[b,h] = sum_g hid[b,g] * aW[g,h], fused split-K.
// grid (8, 16) = 128 blocks (all co-resident), block 128.
// Each block computes a 64-g partial, then the 16 blocks of a column sync on
// a per-column counter and distributedly reduce (2 batches per block).
// aW (4 MB) read exactly once from DRAM.
// ---------------------------------------------------------------------------
__global__ void k_u(const float* __restrict__ hid,
                    const float* __restrict__ aW) {
    const int x = blockIdx.x, y = blockIdx.y;
    const int h  = x * 128 + threadIdx.x;
    const int g0 = y * 64;

    __shared__ float4 s_hid[B][16];                 // 8 KB
    for (int i = threadIdx.x; i < B * 16; i += 128) {
        int b = i >> 4, c = i & 15;
        s_hid[b][c] = ((const float4*)(hid + b * H + g0))[c];
    }
    __syncthreads();

    float acc[B];
#pragma unroll
    for (int b = 0; b < B; b++) acc[b] = 0.f;
#pragma unroll 4
    for (int c = 0; c < 16; c++) {
        const float* ap = aW + (size_t)(g0 + 4 * c) * H + h;
        float a0 = ap[0], a1 = ap[H], a2 = ap[2 * H], a3 = ap[3 * H];
#pragma unroll
        for (int b = 0; b < B; b++) {
            float4 h4 = s_hid[b][c];
            acc[b] = fmaf(a0, h4.x, fmaf(a1, h4.y,
                      fmaf(a2, h4.z, fmaf(a3, h4.w, acc[b]))));
        }
    }
    float* outp = g_part_u + (size_t)y * (B * H) + h;
#pragma unroll
    for (int b = 0; b < B; b++) outp[b * H] = acc[b];

    // ---- per-column arrive + spin (16 blocks, co-resident by construction)
    __threadfence();
    __syncthreads();
    if (threadIdx.x == 0) {
        atomicAdd(&cnt_u1[x], 1u);
        while (atomicAdd(&cnt_u1[x], 0u) < GS) __nanosleep(64);
    }
    __syncthreads();
    __threadfence();

    // ---- distributed reduce: block y sums batches 2y, 2y+1
    const float* base = g_part_u + x * 128 + threadIdx.x;
#pragma unroll
    for (int bb = 0; bb < 2; bb++) {
        const int b = 2 * y + bb;
        float s = 0.f;
#pragma unroll
        for (int q = 0; q < GS; q++) s += base[(size_t)q * (B * H) + b * H];
        g_u[b * H + h] = s;
    }

    // ---- self-resetting exit counter
    __threadfence();
    __syncthreads();
    if (threadIdx.x == 0) {
        if (atomicAdd(&cnt_u2[x], 1u) == GS - 1u) {
            atomicExch(&cnt_u1[x], 0u);
            atomicExch(&cnt_u2[x], 0u);
        }
    }
}

// ---------------------------------------------------------------------------
// Kernel 2: v[b,k] = sum_h u[b,h] * rW[h,k], same fused split-K pattern.
// grid (16, 16) = 256 blocks (co-resident), block 128. rW (8 MB) read once.
// ---------------------------------------------------------------------------
__global__ void k_v(const float* __restrict__ rW) {
    const int x = blockIdx.x, y = blockIdx.y;
    const int k  = x * 128 + threadIdx.x;
    const int h0 = y * 64;

    __shared__ float4 s_u[B][16];                   // 8 KB
    for (int i = threadIdx.x; i < B * 16; i += 128) {
        int b = i >> 4, c = i & 15;
        s_u[b][c] = ((const float4*)(g_u + b * H + h0))[c];
    }
    __syncthreads();

    float acc[B];
#pragma unroll
    for (int b = 0; b < B; b++) acc[b] = 0.f;
#pragma unroll 4
    for (int c = 0; c < 16; c++) {
        const float* rp = rW + (size_t)(h0 + 4 * c) * K2 + k;
        float r0 = rp[0], r1 = rp[K2], r2 = rp[2 * K2], r3 = rp[3 * K2];
#pragma unroll
        for (int b = 0; b < B; b++) {
            float4 u4 = s_u[b][c];
            acc[b] = fmaf(r0, u4.x, fmaf(r1, u4.y,
                      fmaf(r2, u4.z, fmaf(r3, u4.w, acc[b]))));
        }
    }
    float* outp = g_part_v + (size_t)y * (B * K2) + k;
#pragma unroll
    for (int b = 0; b < B; b++) outp[b * K2] = acc[b];

    __threadfence();
    __syncthreads();
    if (threadIdx.x == 0) {
        atomicAdd(&cnt_v1[x], 1u);
        while (atomicAdd(&cnt_v1[x], 0u) < HS) __nanosleep(64);
    }
    __syncthreads();
    __threadfence();

    const float* base = g_part_v + x * 128 + threadIdx.x;
#pragma unroll
    for (int bb = 0; bb < 2; bb++) {
        const int b = 2 * y + bb;
        float s = 0.f;
#pragma unroll
        for (int q = 0; q < HS; q++) s += base[(size_t)q * (B * K2) + b * K2];
        g_v[b * K2 + k] = s;
    }

    __threadfence();
    __syncthreads();
    if (threadIdx.x == 0) {
        if (atomicAdd(&cnt_v2[x], 1u) == HS - 1u) {
            atomicExch(&cnt_v1[x], 0u);
            atomicExch(&cnt_v2[x], 0u);
        }
    }
}

// ---------------------------------------------------------------------------
// Kernel 3 (HBM-bound; body IDENTICAL to R4's 84.5%-DRAM version):
// scores[b,l] = v[b] . enc[l,b,:], then the last-finishing block of each
// batch b runs the row softmax inline (counter-elected, self-resetting).
// grid (L/8, B), block 256, launch_bounds(256,8) -> 32 regs.
// ---------------------------------------------------------------------------
__global__ void __launch_bounds__(256, 8) k_scores(const float* __restrict__ enc,
                                                   float* __restrict__ out) {
    const int b    = blockIdx.y;
    const int w    = threadIdx.x >> 5;
    const int lane = threadIdx.x & 31;

    __shared__ float4 sv[K2 / 4];                   // 8 KB
    const float4* v4 = (const float4*)(g_v + b * K2);
    for (int i = threadIdx.x; i < K2 / 4; i += 256) sv[i] = v4[i];
    __syncthreads();

    const int l = blockIdx.x * 8 + w;
    const float4* e4 = (const float4*)(enc + ((size_t)l * B + b) * K2);

    float4 e[16];
#pragma unroll
    for (int j = 0; j < 16; j++) e[j] = __ldcs(&e4[lane + 32 * j]);

    float ax = 0.f, ay = 0.f, az = 0.f, aw = 0.f;
#pragma unroll
    for (int j = 0; j < 16; j++) {
        float4 vv = sv[lane + 32 * j];
        ax += e[j].x * vv.x; ay += e[j].y * vv.y;
        az += e[j].z * vv.z; aw += e[j].w * vv.w;
    }
    float acc = (ax + ay) + (az + aw);
#pragma unroll
    for (int o = 16; o; o >>= 1)
        acc += __shfl_xor_sync(0xffffffffu, acc, o);
    if (lane == 0) g_scores[b * L + l] = acc;

    // ---- softmax tail: elect the 256th-finishing block of this batch ----
    __threadfence();
    __syncthreads();
    __shared__ unsigned s_last;
    if (threadIdx.x == 0)
        s_last = (atomicAdd(&cnt_s[b], 1u) == (L / 8) - 1u) ? 1u : 0u;
    __syncthreads();
    if (!s_last) return;

    if (threadIdx.x == 0) atomicExch(&cnt_s[b], 0u);   // replay-safe reset
    __threadfence();

    const int tid = threadIdx.x;
    __shared__ float s_red[8];

    float vals[8];
    float m = -INFINITY;
#pragma unroll
    for (int i = 0; i < 8; i++) {
        vals[i] = __ldcg(&g_scores[b * L + tid + i * 256]);
        m = fmaxf(m, vals[i]);
    }
#pragma unroll
    for (int o = 16; o; o >>= 1)
        m = fmaxf(m, __shfl_xor_sync(0xffffffffu, m, o));
    if (lane == 0) s_red[w] = m;
    __syncthreads();
    float bm = s_red[0];
#pragma unroll
    for (int i = 1; i < 8; i++) bm = fmaxf(bm, s_red[i]);
    __syncthreads();

    float s = 0.f;
#pragma unroll
    for (int i = 0; i < 8; i++) { vals[i] = expf(vals[i] - bm); s += vals[i]; }
#pragma unroll
    for (int o = 16; o; o >>= 1) s += __shfl_xor_sync(0xffffffffu, s, o);
    if (lane == 0) s_red[w] = s;
    __syncthreads();
    float bs = 0.f;
#pragma unroll
    for (int i = 0; i < 8; i++) bs += s_red[i];

    const float inv = 1.f / bs;
#pragma unroll
    for (int i = 0; i < 8; i++)
        out[b * L + tid + i * 256] = vals[i] * inv;
}

// ---------------------------------------------------------------------------
extern "C" void kernel_launch(void* const* d_in, const int* in_sizes, int n_in,
                              void* d_out, int out_size) {
    const float* hid = (const float*)d_in[0];  // [B, H]
    const float* enc = (const float*)d_in[1];  // [L, B, 2H]
    const float* rW  = (const float*)d_in[2];  // [H, 2H]
    // d_in[3] = reduce_b, d_in[5] = attn_b: constant per batch over l ->
    // invariant under softmax, provably unused.
    const float* aW  = (const float*)d_in[4];  // [H, H]
    float* out = (float*)d_out;                // [B, L]

    k_u<<<dim3(8, GS), 128>>>(hid, aW);
    k_v<<<dim3(16, HS), 128>>>(rW);
    k_scores<<<dim3(L / 8, B), 256>>>(enc, out);
}

// round 9
// speedup vs baseline: 1.0149x; 1.0149x over previous
#include <cuda_runtime.h>
#include <math.h>

#define B  32
#define L  2048
#define H  1024
#define K2 2048   // 2*H

#define GS 32     // g-splits for u
#define HS 16     // h-splits for v

// Scratch (no allocations allowed anywhere)
__device__ float g_part_u[GS * B * H];    // 4 MB  (L2-hot)
__device__ float g_u[B * H];              // 128 KB
__device__ float g_part_v[HS * B * K2];   // 4 MB  (L2-hot)
__device__ float g_v[B * K2];             // 256 KB
__device__ float g_scores[B * L];         // 256 KB

// Arrival counters (zero-init; kernels leave them at zero -> replay-safe)
__device__ unsigned cnt_v1[16], cnt_v2[16];
__device__ unsigned cnt_s[B];

// ---------------------------------------------------------------------------
// Kernel 1: partial u[b,h] = sum_{g in 32-chunk} hid[b,g] * aW[g,h]
// grid (8, 32) = 256 blocks (2/SM), block 128. aW (4 MB) read exactly once.
// Also prefetches ALL of rW (8 MB) into L2 so kernel 3's reads are L2 hits
// (k_u uses <3% of DRAM BW, so the prefetch rides in its latency bubbles).
// ---------------------------------------------------------------------------
__global__ void k_u_partial(const float* __restrict__ hid,
                            const float* __restrict__ aW,
                            const float* __restrict__ rW) {
    // L2 prefetch of rW: 32768 threads x 64 floats = 2M floats = 8 MB
    {
        const int gt = (blockIdx.y * 8 + blockIdx.x) * 128 + threadIdx.x;
        const float* p = rW + (size_t)gt * 64;
        asm volatile("prefetch.global.L2 [%0];" :: "l"(p));
        asm volatile("prefetch.global.L2 [%0];" :: "l"(p + 32));
    }

    const int h  = blockIdx.x * 128 + threadIdx.x;
    const int g0 = blockIdx.y * 32;
    __shared__ float4 s_hid[B][8];                  // 4 KB
    for (int i = threadIdx.x; i < B * 8; i += 128) {
        int b = i >> 3, c = i & 7;
        s_hid[b][c] = ((const float4*)(hid + b * H + g0))[c];
    }
    __syncthreads();

    float acc[B];
#pragma unroll
    for (int b = 0; b < B; b++) acc[b] = 0.f;
#pragma unroll 4
    for (int c = 0; c < 8; c++) {
        const float* ap = aW + (size_t)(g0 + 4 * c) * H + h;
        float a0 = ap[0], a1 = ap[H], a2 = ap[2 * H], a3 = ap[3 * H];
#pragma unroll
        for (int b = 0; b < B; b++) {
            float4 h4 = s_hid[b][c];
            acc[b] = fmaf(a0, h4.x, fmaf(a1, h4.y,
                      fmaf(a2, h4.z, fmaf(a3, h4.w, acc[b]))));
        }
    }
    float* outp = g_part_u + (size_t)blockIdx.y * (B * H) + h;
#pragma unroll
    for (int b = 0; b < B; b++) outp[b * H] = acc[b];
}

// ---------------------------------------------------------------------------
// Kernel 2: u = sum over GS=32 partials. Lane-split: 4 threads per float4
// output, 8 sequential loads each, shfl-combined (deterministic).
// 32768 threads = 128 blocks x 256. Partials are L2-hot (4 MB).
// ---------------------------------------------------------------------------
__global__ void k_u_reduce() {
    const int t = blockIdx.x * 256 + threadIdx.x;
    const int o = t >> 2;                 // output float4 index (0..8191)
    const int p = (t & 3) * 8;            // my 8-partial chunk
    const float4* base = (const float4*)g_part_u + o;
    float4 s = make_float4(0.f, 0.f, 0.f, 0.f);
#pragma unroll
    for (int j = 0; j < 8; j++) {
        float4 x = base[(size_t)(p + j) * (B * H / 4)];
        s.x += x.x; s.y += x.y; s.z += x.z; s.w += x.w;
    }
#pragma unroll
    for (int off = 1; off <= 2; off <<= 1) {
        s.x += __shfl_xor_sync(0xffffffffu, s.x, off);
        s.y += __shfl_xor_sync(0xffffffffu, s.y, off);
        s.z += __shfl_xor_sync(0xffffffffu, s.z, off);
        s.w += __shfl_xor_sync(0xffffffffu, s.w, off);
    }
    if ((t & 3) == 0) ((float4*)g_u)[o] = s;
}

// ---------------------------------------------------------------------------
// Kernel 3 (IDENTICAL to R8's k_v, which measured ~5us): fused split-K
// v[b,k] = sum_h u[b,h] * rW[h,k]. grid (16, 16) = 256 blocks, block 128.
// rW reads are now L2 hits thanks to kernel 1's prefetch.
// ---------------------------------------------------------------------------
__global__ void k_v(const float* __restrict__ rW) {
    const int x = blockIdx.x, y = blockIdx.y;
    const int k  = x * 128 + threadIdx.x;
    const int h0 = y * 64;

    __shared__ float4 s_u[B][16];                   // 8 KB
    for (int i = threadIdx.x; i < B * 16; i += 128) {
        int b = i >> 4, c = i & 15;
        s_u[b][c] = ((const float4*)(g_u + b * H + h0))[c];
    }
    __syncthreads();

    float acc[B];
#pragma unroll
    for (int b = 0; b < B; b++) acc[b] = 0.f;
#pragma unroll 4
    for (int c = 0; c < 16; c++) {
        const float* rp = rW + (size_t)(h0 + 4 * c) * K2 + k;
        float r0 = rp[0], r1 = rp[K2], r2 = rp[2 * K2], r3 = rp[3 * K2];
#pragma unroll
        for (int b = 0; b < B; b++) {
            float4 u4 = s_u[b][c];
            acc[b] = fmaf(r0, u4.x, fmaf(r1, u4.y,
                      fmaf(r2, u4.z, fmaf(r3, u4.w, acc[b]))));
        }
    }
    float* outp = g_part_v + (size_t)y * (B * K2) + k;
#pragma unroll
    for (int b = 0; b < B; b++) outp[b * K2] = acc[b];

    __threadfence();
    __syncthreads();
    if (threadIdx.x == 0) {
        atomicAdd(&cnt_v1[x], 1u);
        while (atomicAdd(&cnt_v1[x], 0u) < HS) __nanosleep(64);
    }
    __syncthreads();
    __threadfence();

    const float* base = g_part_v + x * 128 + threadIdx.x;
#pragma unroll
    for (int bb = 0; bb < 2; bb++) {
        const int b = 2 * y + bb;
        float s = 0.f;
#pragma unroll
        for (int q = 0; q < HS; q++) s += base[(size_t)q * (B * K2) + b * K2];
        g_v[b * K2 + k] = s;
    }

    __threadfence();
    __syncthreads();
    if (threadIdx.x == 0) {
        if (atomicAdd(&cnt_v2[x], 1u) == HS - 1u) {
            atomicExch(&cnt_v1[x], 0u);
            atomicExch(&cnt_v2[x], 0u);
        }
    }
}

// ---------------------------------------------------------------------------
// Kernel 4 (HBM-bound; body IDENTICAL to R4's 84.5%-DRAM version):
// scores[b,l] = v[b] . enc[l,b,:], then the last-finishing block of each
// batch b runs the row softmax inline (counter-elected, self-resetting).
// grid (L/8, B), block 256, launch_bounds(256,8) -> 32 regs.
// ---------------------------------------------------------------------------
__global__ void __launch_bounds__(256, 8) k_scores(const float* __restrict__ enc,
                                                   float* __restrict__ out) {
    const int b    = blockIdx.y;
    const int w    = threadIdx.x >> 5;
    const int lane = threadIdx.x & 31;

    __shared__ float4 sv[K2 / 4];                   // 8 KB
    const float4* v4 = (const float4*)(g_v + b * K2);
    for (int i = threadIdx.x; i < K2 / 4; i += 256) sv[i] = v4[i];
    __syncthreads();

    const int l = blockIdx.x * 8 + w;
    const float4* e4 = (const float4*)(enc + ((size_t)l * B + b) * K2);

    float4 e[16];
#pragma unroll
    for (int j = 0; j < 16; j++) e[j] = __ldcs(&e4[lane + 32 * j]);

    float ax = 0.f, ay = 0.f, az = 0.f, aw = 0.f;
#pragma unroll
    for (int j = 0; j < 16; j++) {
        float4 vv = sv[lane + 32 * j];
        ax += e[j].x * vv.x; ay += e[j].y * vv.y;
        az += e[j].z * vv.z; aw += e[j].w * vv.w;
    }
    float acc = (ax + ay) + (az + aw);
#pragma unroll
    for (int o = 16; o; o >>= 1)
        acc += __shfl_xor_sync(0xffffffffu, acc, o);
    if (lane == 0) g_scores[b * L + l] = acc;

    // ---- softmax tail: elect the 256th-finishing block of this batch ----
    __threadfence();
    __syncthreads();
    __shared__ unsigned s_last;
    if (threadIdx.x == 0)
        s_last = (atomicAdd(&cnt_s[b], 1u) == (L / 8) - 1u) ? 1u : 0u;
    __syncthreads();
    if (!s_last) return;

    if (threadIdx.x == 0) atomicExch(&cnt_s[b], 0u);   // replay-safe reset
    __threadfence();

    const int tid = threadIdx.x;
    __shared__ float s_red[8];

    float vals[8];
    float m = -INFINITY;
#pragma unroll
    for (int i = 0; i < 8; i++) {
        vals[i] = __ldcg(&g_scores[b * L + tid + i * 256]);
        m = fmaxf(m, vals[i]);
    }
#pragma unroll
    for (int o = 16; o; o >>= 1)
        m = fmaxf(m, __shfl_xor_sync(0xffffffffu, m, o));
    if (lane == 0) s_red[w] = m;
    __syncthreads();
    float bm = s_red[0];
#pragma unroll
    for (int i = 1; i < 8; i++) bm = fmaxf(bm, s_red[i]);
    __syncthreads();

    float s = 0.f;
#pragma unroll
    for (int i = 0; i < 8; i++) { vals[i] = expf(vals[i] - bm); s += vals[i]; }
#pragma unroll
    for (int o = 16; o; o >>= 1) s += __shfl_xor_sync(0xffffffffu, s, o);
    if (lane == 0) s_red[w] = s;
    __syncthreads();
    float bs = 0.f;
#pragma unroll
    for (int i = 0; i < 8; i++) bs += s_red[i];

    const float inv = 1.f / bs;
#pragma unroll
    for (int i = 0; i < 8; i++)
        out[b * L + tid + i * 256] = vals[i] * inv;
}

// ---------------------------------------------------------------------------
extern "C" void kernel_launch(void* const* d_in, const int* in_sizes, int n_in,
                              void* d_out, int out_size) {
    const float* hid = (const float*)d_in[0];  // [B, H]
    const float* enc = (const float*)d_in[1];  // [L, B, 2H]
    const float* rW  = (const float*)d_in[2];  // [H, 2H]
    // d_in[3] = reduce_b, d_in[5] = attn_b: constant per batch over l ->
    // invariant under softmax, provably unused.
    const float* aW  = (const float*)d_in[4];  // [H, H]
    float* out = (float*)d_out;                // [B, L]

    k_u_partial<<<dim3(8, GS), 128>>>(hid, aW, rW);
    k_u_reduce<<<128, 256>>>();
    k_v<<<dim3(16, HS), 128>>>(rW);
    k_scores<<<dim3(L / 8, B), 256>>>(enc, out);
}

// round 10
// speedup vs baseline: 1.0798x; 1.0639x over previous
#include <cuda_runtime.h>
#include <math.h>

#define B  32
#define L  2048
#define H  1024
#define K2 2048   // 2*H

#define GS 32     // g-splits for u
#define HS 32     // h-splits for v

// Scratch (no allocations allowed anywhere)
__device__ float g_part_u[GS * B * H];    // 4 MB  (L2-hot)
__device__ float g_u[B * H];              // 128 KB
__device__ float g_part_v[HS * B * K2];   // 8 MB  (L2-hot)
__device__ float g_v[B * K2];             // 256 KB
__device__ float g_scores[B * L];         // 256 KB

// Arrival counters (zero-init; kernels leave them at zero -> replay-safe)
__device__ unsigned cnt_s[B];

// ---------------------------------------------------------------------------
// Kernel 1: partial u[b,h] = sum_{g in 32-chunk} hid[b,g] * aW[g,h]
// grid (8, 32) = 256 blocks, block 128. aW (4 MB) read exactly once, with
// ALL 32 strided loads per thread issued back-to-back BEFORE any FMA
// (1024 warps x 4 KB outstanding = 4 MB in flight -> BW-saturated even on
// cold DRAM). Also prefetches all of rW (8 MB) into L2 for kernel 3.
// ---------------------------------------------------------------------------
__global__ void k_u_partial(const float* __restrict__ hid,
                            const float* __restrict__ aW,
                            const float* __restrict__ rW) {
    // L2 prefetch of rW: 32768 threads x 64 floats = 8 MB
    {
        const int gt = (blockIdx.y * 8 + blockIdx.x) * 128 + threadIdx.x;
        const float* p = rW + (size_t)gt * 64;
        asm volatile("prefetch.global.L2 [%0];" :: "l"(p));
        asm volatile("prefetch.global.L2 [%0];" :: "l"(p + 32));
    }

    const int h  = blockIdx.x * 128 + threadIdx.x;
    const int g0 = blockIdx.y * 32;

    // ---- batch ALL aW loads first (32 independent strided LDGs) ----
    float a[32];
    {
        const float* ap = aW + (size_t)g0 * H + h;
#pragma unroll
        for (int j = 0; j < 32; j++) a[j] = ap[(size_t)j * H];
    }

    __shared__ float4 s_hid[B][8];                  // 4 KB
    for (int i = threadIdx.x; i < B * 8; i += 128) {
        int b = i >> 3, c = i & 7;
        s_hid[b][c] = ((const float4*)(hid + b * H + g0))[c];
    }
    __syncthreads();

    float acc[B];
#pragma unroll
    for (int b = 0; b < B; b++) acc[b] = 0.f;
#pragma unroll
    for (int c = 0; c < 8; c++) {
#pragma unroll
        for (int b = 0; b < B; b++) {
            float4 h4 = s_hid[b][c];
            acc[b] = fmaf(a[4 * c + 0], h4.x, fmaf(a[4 * c + 1], h4.y,
                      fmaf(a[4 * c + 2], h4.z, fmaf(a[4 * c + 3], h4.w, acc[b]))));
        }
    }
    float* outp = g_part_u + (size_t)blockIdx.y * (B * H) + h;
#pragma unroll
    for (int b = 0; b < B; b++) outp[b * H] = acc[b];
}

// ---------------------------------------------------------------------------
// Kernel 2: u = sum over GS=32 partials. Lane-split: 4 threads per float4
// output, 8 loads each, shfl-combined (deterministic). L2-hot partials.
// ---------------------------------------------------------------------------
__global__ void k_u_reduce() {
    const int t = blockIdx.x * 256 + threadIdx.x;   // 32768 threads
    const int o = t >> 2;                 // output float4 index (0..8191)
    const int p = (t & 3) * 8;
    const float4* base = (const float4*)g_part_u + o;
    float4 s = make_float4(0.f, 0.f, 0.f, 0.f);
#pragma unroll
    for (int j = 0; j < 8; j++) {
        float4 x = base[(size_t)(p + j) * (B * H / 4)];
        s.x += x.x; s.y += x.y; s.z += x.z; s.w += x.w;
    }
#pragma unroll
    for (int off = 1; off <= 2; off <<= 1) {
        s.x += __shfl_xor_sync(0xffffffffu, s.x, off);
        s.y += __shfl_xor_sync(0xffffffffu, s.y, off);
        s.z += __shfl_xor_sync(0xffffffffu, s.z, off);
        s.w += __shfl_xor_sync(0xffffffffu, s.w, off);
    }
    if ((t & 3) == 0) ((float4*)g_u)[o] = s;
}

// ---------------------------------------------------------------------------
// Kernel 3: partial v[b,k] = sum_{h in 32-chunk} u[b,h] * rW[h,k]
// grid (16, 32) = 512 blocks, block 128. Batch-32 rW loads (L2-hit thanks to
// kernel 1's prefetch), then FMAs.
// ---------------------------------------------------------------------------
__global__ void k_v_partial(const float* __restrict__ rW) {
    const int k  = blockIdx.x * 128 + threadIdx.x;
    const int h0 = blockIdx.y * 32;

    float r[32];
    {
        const float* rp = rW + (size_t)h0 * K2 + k;
#pragma unroll
        for (int j = 0; j < 32; j++) r[j] = rp[(size_t)j * K2];
    }

    __shared__ float4 s_u[B][8];                    // 4 KB
    for (int i = threadIdx.x; i < B * 8; i += 128) {
        int b = i >> 3, c = i & 7;
        s_u[b][c] = ((const float4*)(g_u + b * H + h0))[c];
    }
    __syncthreads();

    float acc[B];
#pragma unroll
    for (int b = 0; b < B; b++) acc[b] = 0.f;
#pragma unroll
    for (int c = 0; c < 8; c++) {
#pragma unroll
        for (int b = 0; b < B; b++) {
            float4 u4 = s_u[b][c];
            acc[b] = fmaf(r[4 * c + 0], u4.x, fmaf(r[4 * c + 1], u4.y,
                      fmaf(r[4 * c + 2], u4.z, fmaf(r[4 * c + 3], u4.w, acc[b]))));
        }
    }
    float* outp = g_part_v + (size_t)blockIdx.y * (B * K2) + k;
#pragma unroll
    for (int b = 0; b < B; b++) outp[b * K2] = acc[b];
}

// ---------------------------------------------------------------------------
// Kernel 4: v = sum over HS=32 partials. Lane-split 4x8, 65536 threads.
// ---------------------------------------------------------------------------
__global__ void k_v_reduce() {
    const int t = blockIdx.x * 256 + threadIdx.x;   // 65536 threads
    const int o = t >> 2;                 // output float4 index (0..16383)
    const int p = (t & 3) * 8;
    const float4* base = (const float4*)g_part_v + o;
    float4 s = make_float4(0.f, 0.f, 0.f, 0.f);
#pragma unroll
    for (int j = 0; j < 8; j++) {
        float4 x = base[(size_t)(p + j) * (B * K2 / 4)];
        s.x += x.x; s.y += x.y; s.z += x.z; s.w += x.w;
    }
#pragma unroll
    for (int off = 1; off <= 2; off <<= 1) {
        s.x += __shfl_xor_sync(0xffffffffu, s.x, off);
        s.y += __shfl_xor_sync(0xffffffffu, s.y, off);
        s.z += __shfl_xor_sync(0xffffffffu, s.z, off);
        s.w += __shfl_xor_sync(0xffffffffu, s.w, off);
    }
    if ((t & 3) == 0) ((float4*)g_v)[o] = s;
}

// ---------------------------------------------------------------------------
// Kernel 5 (HBM-bound; score body IDENTICAL to R4's 84.5%-DRAM version):
// scores[b,l] = v[b] . enc[l,b,:], then the last-finishing block of each
// batch b runs the row softmax inline (counter-elected, self-resetting).
// grid (L/8, B), block 256, launch_bounds(256,8) -> 32 regs.
// ---------------------------------------------------------------------------
__global__ void __launch_bounds__(256, 8) k_scores(const float* __restrict__ enc,
                                                   float* __restrict__ out) {
    const int b    = blockIdx.y;
    const int w    = threadIdx.x >> 5;
    const int lane = threadIdx.x & 31;

    __shared__ float4 sv[K2 / 4];                   // 8 KB
    const float4* v4 = (const float4*)(g_v + b * K2);
    for (int i = threadIdx.x; i < K2 / 4; i += 256) sv[i] = v4[i];
    __syncthreads();

    const int l = blockIdx.x * 8 + w;
    const float4* e4 = (const float4*)(enc + ((size_t)l * B + b) * K2);

    float4 e[16];
#pragma unroll
    for (int j = 0; j < 16; j++) e[j] = __ldcs(&e4[lane + 32 * j]);

    float ax = 0.f, ay = 0.f, az = 0.f, aw = 0.f;
#pragma unroll
    for (int j = 0; j < 16; j++) {
        float4 vv = sv[lane + 32 * j];
        ax += e[j].x * vv.x; ay += e[j].y * vv.y;
        az += e[j].z * vv.z; aw += e[j].w * vv.w;
    }
    float acc = (ax + ay) + (az + aw);
#pragma unroll
    for (int o = 16; o; o >>= 1)
        acc += __shfl_xor_sync(0xffffffffu, acc, o);
    if (lane == 0) g_scores[b * L + l] = acc;

    // ---- softmax tail: elect the 256th-finishing block of this batch ----
    __threadfence();
    __syncthreads();
    __shared__ unsigned s_last;
    if (threadIdx.x == 0)
        s_last = (atomicAdd(&cnt_s[b], 1u) == (L / 8) - 1u) ? 1u : 0u;
    __syncthreads();
    if (!s_last) return;

    if (threadIdx.x == 0) atomicExch(&cnt_s[b], 0u);   // replay-safe reset
    __threadfence();

    const int tid = threadIdx.x;
    __shared__ float s_red[8];

    float vals[8];
    float m = -INFINITY;
#pragma unroll
    for (int i = 0; i < 8; i++) {
        vals[i] = __ldcg(&g_scores[b * L + tid + i * 256]);
        m = fmaxf(m, vals[i]);
    }
#pragma unroll
    for (int o = 16; o; o >>= 1)
        m = fmaxf(m, __shfl_xor_sync(0xffffffffu, m, o));
    if (lane == 0) s_red[w] = m;
    __syncthreads();
    float bm = s_red[0];
#pragma unroll
    for (int i = 1; i < 8; i++) bm = fmaxf(bm, s_red[i]);
    __syncthreads();

    float s = 0.f;
#pragma unroll
    for (int i = 0; i < 8; i++) { vals[i] = expf(vals[i] - bm); s += vals[i]; }
#pragma unroll
    for (int o = 16; o; o >>= 1) s += __shfl_xor_sync(0xffffffffu, s, o);
    if (lane == 0) s_red[w] = s;
    __syncthreads();
    float bs = 0.f;
#pragma unroll
    for (int i = 0; i < 8; i++) bs += s_red[i];

    const float inv = 1.f / bs;
#pragma unroll
    for (int i = 0; i < 8; i++)
        out[b * L + tid + i * 256] = vals[i] * inv;
}

// ---------------------------------------------------------------------------
extern "C" void kernel_launch(void* const* d_in, const int* in_sizes, int n_in,
                              void* d_out, int out_size) {
    const float* hid = (const float*)d_in[0];  // [B, H]
    const float* enc = (const float*)d_in[1];  // [L, B, 2H]
    const float* rW  = (const float*)d_in[2];  // [H, 2H]
    // d_in[3] = reduce_b, d_in[5] = attn_b: constant per batch over l ->
    // invariant under softmax, provably unused.
    const float* aW  = (const float*)d_in[4];  // [H, H]
    float* out = (float*)d_out;                // [B, L]

    k_u_partial<<<dim3(8, GS), 128>>>(hid, aW, rW);
    k_u_reduce<<<128, 256>>>();
    k_v_partial<<<dim3(16, HS), 128>>>(rW);
    k_v_reduce<<<256, 256>>>();
    k_scores<<<dim3(L / 8, B), 256>>>(enc, out);
}